// round 14
// baseline (speedup 1.0000x reference)
#include <cuda_runtime.h>
#include <cuda_fp16.h>

// TropConv2D: out[pos,f] = max_k(p_k + w[k][f]) - min_k(p_k + w[k][f]) + bias[f]
// fp16x2 inner loop; 384 threads (1 pos x 4 filters each), 300 CTAs x 24 positions,
// w in smem with both filter-pairs interleaved per fg-row (16B-aligned stride 68).
#define KH 3
#define KW 3
#define CH 32
#define NF 64
#define HH 32
#define WW 32
#define HO 30
#define WO 30

#define WT_ROW   68                       // half2 stride per (ij,fg) row (64 used + 4 pad)
// layout: w_h[(ij*16 + fg)*68 + 2c + slot], slot0 = pair (4fg,4fg+1), slot1 = (4fg+2,4fg+3)
#define WT_TOTAL (9*16*WT_ROW)            // 9792 half2
#define XSEG_H2  (3*WW*CH)                // 3072 half2 : one 3-row triple, (p,p) broadcast
#define SMEM_H2  (WT_TOTAL + 2*XSEG_H2)   // 16032... wait 9792+6144 = 15936
#define SMEM_BYTES (SMEM_H2*4)            // 63744

#define NTHREADS 384
#define NCTA 300                          // 300 * 24 = 7200 positions exactly
#define POS_PER_CTA 24

__device__ __forceinline__ __half2 as_h2(unsigned u) {
    return *reinterpret_cast<const __half2*>(&u);
}

// one channel, both filter-pairs
#define UPDC(PH, WA, WB, MX0, MN0, MX1, MN1) do {   \
    __half2 sa_ = __hadd2((PH), (WA));              \
    __half2 sb_ = __hadd2((PH), (WB));              \
    (MX0) = __hmax2((MX0), sa_);                    \
    (MN0) = __hmin2((MN0), sa_);                    \
    (MX1) = __hmax2((MX1), sb_);                    \
    (MN1) = __hmin2((MN1), sb_);                    \
  } while (0)

__global__ __launch_bounds__(NTHREADS, 2)
void tropconv_kernel(const float* __restrict__ x,
                     const float* __restrict__ w,
                     const float* __restrict__ bias,
                     float* __restrict__ out)
{
    extern __shared__ unsigned smem[];           // address in u32/half2 units
    unsigned* w_h = smem;                        // [9][16][WT_ROW] packed half2
    unsigned* x_s = smem + WT_TOTAL;             // [2][3*WW*CH] broadcast (p,p) half2

    const int tid = threadIdx.x;
    const int cta = blockIdx.x;

    const int start = POS_PER_CTA * cta;
    const int row0  = start / WO;
    const int row1  = (start + POS_PER_CTA - 1) / WO;

    // ---- w -> packed half2, interleaved pairs: w_h[(ij*16+q)*68 + 2c + slot] ----
    {
        const float4* wg = (const float4*)w;
        #pragma unroll
        for (int it = 0; it < 12; it++) {        // 4608 float4 / 384 threads
            int v = tid + NTHREADS * it;         // k = v>>4 (0..287), quad q = v&15
            float4 t = wg[v];
            int k  = v >> 4;
            int q  = v & 15;
            int ij = k >> 5;
            int c  = k & 31;
            __half2 pa = __floats2half2_rn(t.x, t.y);   // filters 4q,4q+1
            __half2 pb = __floats2half2_rn(t.z, t.w);   // filters 4q+2,4q+3
            unsigned* dst = w_h + (ij * 16 + q) * WT_ROW + 2 * c;
            dst[0] = *reinterpret_cast<unsigned*>(&pa);
            dst[1] = *reinterpret_cast<unsigned*>(&pb);
        }
    }
    // ---- 2 input row-triples -> broadcast half2 (768 float4 each, 2 per thread) ----
    #pragma unroll
    for (int s = 0; s < 2; s++) {
        int rf = s ? row1 : row0;
        int bb = rf / HO;
        int hh = rf - bb * HO;
        const float4* src = (const float4*)(x + (size_t)(bb * HH + hh) * (WW * CH));
        unsigned* dst = x_s + s * XSEG_H2;
        #pragma unroll
        for (int i = 0; i < 2; i++) {
            int v = tid + NTHREADS * i;
            float4 t = src[v];
            __half2 a = __floats2half2_rn(t.x, t.x);
            __half2 b = __floats2half2_rn(t.y, t.y);
            __half2 c = __floats2half2_rn(t.z, t.z);
            __half2 d = __floats2half2_rn(t.w, t.w);
            uint4 o;
            o.x = *reinterpret_cast<unsigned*>(&a);
            o.y = *reinterpret_cast<unsigned*>(&b);
            o.z = *reinterpret_cast<unsigned*>(&c);
            o.w = *reinterpret_cast<unsigned*>(&d);
            *(uint4*)(dst + v * 4) = o;
        }
    }
    __syncthreads();

    // thread = (pp 0..23, fg 0..15): position start+pp, filters 4fg..4fg+3
    const int fg = tid & 15;
    const int pp = tid >> 4;
    const int f0 = fg * 4;

    const int pos  = start + pp;
    const int rowf = pos / WO;
    const int wo   = pos - rowf * WO;
    const unsigned* xb = x_s + (rowf != row0 ? XSEG_H2 : 0) + wo * CH;

    const __half2 NEGI = __float2half2_rn(-65504.f);
    const __half2 POSI = __float2half2_rn( 65504.f);
    __half2 mx0 = NEGI, mx1 = NEGI, mn0 = POSI, mn1 = POSI;

    const unsigned* wt_fg = w_h + fg * WT_ROW;   // + ij*16*WT_ROW per ij

    #pragma unroll 1
    for (int i = 0; i < KH; i++) {
        const unsigned* prow = xb + i * (WW * CH);
        #pragma unroll
        for (int j = 0; j < KW; j++) {
            const int ij = i * 3 + j;
            const uint4* pr = (const uint4*)(prow + j * CH);
            const unsigned* wr = wt_fg + ij * (16 * WT_ROW);

            #pragma unroll
            for (int c = 0; c < CH; c += 4) {
                uint4 P  = pr[c >> 2];
                uint4 W0 = *(const uint4*)(wr + 2 * c);       // (a(c),b(c),a(c+1),b(c+1))
                uint4 W1 = *(const uint4*)(wr + 2 * c + 4);   // (a(c+2),b(c+2),a(c+3),b(c+3))
                UPDC(as_h2(P.x), as_h2(W0.x), as_h2(W0.y), mx0, mn0, mx1, mn1);
                UPDC(as_h2(P.y), as_h2(W0.z), as_h2(W0.w), mx0, mn0, mx1, mn1);
                UPDC(as_h2(P.z), as_h2(W1.x), as_h2(W1.y), mx0, mn0, mx1, mn1);
                UPDC(as_h2(P.w), as_h2(W1.z), as_h2(W1.w), mx0, mn0, mx1, mn1);
            }
        }
    }

    const float4 bi = *(const float4*)(bias + f0);

    float2 a = __half22float2(mx0), b = __half22float2(mn0);
    float2 c = __half22float2(mx1), d = __half22float2(mn1);
    float4 r;
    r.x = a.x - b.x + bi.x;
    r.y = a.y - b.y + bi.y;
    r.z = c.x - d.x + bi.z;
    r.w = c.y - d.y + bi.w;
    *(float4*)(out + (size_t)pos * NF + f0) = r;
}

extern "C" void kernel_launch(void* const* d_in, const int* in_sizes, int n_in,
                              void* d_out, int out_size)
{
    const float* x    = (const float*)d_in[0];
    const float* w    = (const float*)d_in[1];
    const float* bias = (const float*)d_in[2];
    float*       out  = (float*)d_out;

    cudaFuncSetAttribute(tropconv_kernel,
                         cudaFuncAttributeMaxDynamicSharedMemorySize, SMEM_BYTES);
    tropconv_kernel<<<NCTA, NTHREADS, SMEM_BYTES>>>(x, w, bias, out);
}